// round 4
// baseline (speedup 1.0000x reference)
#include <cuda_runtime.h>
#include <math.h>

// Problem constants (B=4, S=4096, D=2048, E=8, K=2)
#define NTOK    16384
#define DIM     2048
#define NEXP    8
#define NASSIGN (NTOK*2)       // 32768
#define CAP     5120           // int(NTOK*2/8 * 1.25)
#define NBLK    (NTOK/32)      // 512 blocks, 32 tokens each

// Output layout (float32): [0,32768) indices | [32768,65536) weights |
// [65536] loss | [65537,98305) mask

// Scratch: __device__ globals (zero-init at load; last block resets after use
// so every graph replay sees zeros).
__device__ int      g_cnt[NEXP];
__device__ float    g_probsum[NEXP];
__device__ unsigned g_done;
__device__ unsigned long long g_bucket[NEXP][NASSIGN];

// Packed fp32x2 FMA (Blackwell): d = a*b + d on two f32 lanes.
__device__ __forceinline__ void ffma2(unsigned long long& d,
                                      unsigned long long a,
                                      unsigned long long b) {
    asm("fma.rn.f32x2 %0, %1, %2, %0;" : "+l"(d) : "l"(a), "l"(b));
}
__device__ __forceinline__ unsigned long long pack2(float a, float b) {
    unsigned long long r;
    asm("mov.b64 %0, {%1, %2};" : "=l"(r) : "f"(a), "f"(b));
    return r;
}
__device__ __forceinline__ float unpack_sum(unsigned long long v) {
    unsigned lo, hi;
    asm("mov.b64 {%0, %1}, %2;" : "=r"(lo), "=r"(hi) : "l"(v));
    return __uint_as_float(lo) + __uint_as_float(hi);
}

// Single fused kernel: GEMV + softmax + top-2 + renorm + stats; the LAST
// arriving block computes the loss + (rare) capacity drop + resets scratch.
__global__ __launch_bounds__(256, 2)
void router_main(const float* __restrict__ x,
                 const float* __restrict__ wg,
                 float* __restrict__ out) {
    extern __shared__ float sw[];              // 8*2048 f32 = 64 KB
    __shared__ float s_prob[NEXP];
    __shared__ int   s_last;

    int tid = threadIdx.x;
    if (tid < NEXP) s_prob[tid] = 0.0f;

    // stage w_gate into shared (L2-resident after first wave)
    float4* sw4 = (float4*)sw;
    const float4* wg4 = (const float4*)wg;
    #pragma unroll
    for (int i = tid; i < NEXP * DIM / 4; i += 256) sw4[i] = wg4[i];
    __syncthreads();

    const int warp = tid >> 5;
    const int lane = tid & 31;
    const int tbase = (blockIdx.x * 8 + warp) * 4;

    const float4* xf0 = (const float4*)(x + (size_t)(tbase + 0) * DIM);
    const float4* xf1 = (const float4*)(x + (size_t)(tbase + 1) * DIM);
    const float4* xf2 = (const float4*)(x + (size_t)(tbase + 2) * DIM);
    const float4* xf3 = (const float4*)(x + (size_t)(tbase + 3) * DIM);
    const ulonglong2* sw2 = (const ulonglong2*)sw;

    unsigned long long acc[4][NEXP];
    #pragma unroll
    for (int t = 0; t < 4; t++)
        #pragma unroll
        for (int e = 0; e < NEXP; e++) acc[t][e] = 0ull;

    // Double-buffered x prefetch: next chunk's 4 LDG.128 issued before the
    // current chunk's FFMA2/LDS block, keeping >=8 loads in flight per warp.
    float4 p0 = __ldcs(xf0 + lane);
    float4 p1 = __ldcs(xf1 + lane);
    float4 p2 = __ldcs(xf2 + lane);
    float4 p3 = __ldcs(xf3 + lane);

    #pragma unroll 4
    for (int i = 0; i < 16; i++) {
        float4 c0 = p0, c1 = p1, c2 = p2, c3 = p3;
        if (i < 15) {
            int nc = (i + 1) * 32 + lane;
            p0 = __ldcs(xf0 + nc);
            p1 = __ldcs(xf1 + nc);
            p2 = __ldcs(xf2 + nc);
            p3 = __ldcs(xf3 + nc);
        }
        unsigned long long xa0 = pack2(c0.x, c0.y), xb0 = pack2(c0.z, c0.w);
        unsigned long long xa1 = pack2(c1.x, c1.y), xb1 = pack2(c1.z, c1.w);
        unsigned long long xa2 = pack2(c2.x, c2.y), xb2 = pack2(c2.z, c2.w);
        unsigned long long xa3 = pack2(c3.x, c3.y), xb3 = pack2(c3.z, c3.w);
        int c = i * 32 + lane;
        #pragma unroll
        for (int e = 0; e < NEXP; e++) {
            ulonglong2 wv = sw2[e * (DIM / 4) + c];
            ffma2(acc[0][e], xa0, wv.x); ffma2(acc[0][e], xb0, wv.y);
            ffma2(acc[1][e], xa1, wv.x); ffma2(acc[1][e], xb1, wv.y);
            ffma2(acc[2][e], xa2, wv.x); ffma2(acc[2][e], xb2, wv.y);
            ffma2(acc[3][e], xa3, wv.x); ffma2(acc[3][e], xb3, wv.y);
        }
    }

    // Collapse f32x2 halves, butterfly-reduce so lanes 0-3 hold full logits.
    float logit[4][NEXP];
    #pragma unroll
    for (int t = 0; t < 4; t++)
        #pragma unroll
        for (int e = 0; e < NEXP; e++) {
            float v = unpack_sum(acc[t][e]);
            v += __shfl_xor_sync(0xffffffffu, v, 16);
            v += __shfl_xor_sync(0xffffffffu, v, 8);
            v += __shfl_xor_sync(0xffffffffu, v, 4);
            v += __shfl_xor_sync(0xffffffffu, v, 2);
            v += __shfl_xor_sync(0xffffffffu, v, 1);
            logit[t][e] = v;
        }

    if (lane < 4) {
        int token = tbase + lane;
        float p[NEXP];
        float m = logit[lane][0];
        #pragma unroll
        for (int e = 1; e < NEXP; e++) m = fmaxf(m, logit[lane][e]);
        float s = 0.0f;
        #pragma unroll
        for (int e = 0; e < NEXP; e++) { p[e] = expf(logit[lane][e] - m); s += p[e]; }
        float inv = 1.0f / s;
        #pragma unroll
        for (int e = 0; e < NEXP; e++) p[e] *= inv;

        // top-2, ties -> lowest index
        int i1 = 0; float b1 = p[0];
        #pragma unroll
        for (int e = 1; e < NEXP; e++) if (p[e] > b1) { b1 = p[e]; i1 = e; }
        int i2 = -1; float b2 = -1.0f;
        #pragma unroll
        for (int e = 0; e < NEXP; e++) if (e != i1 && p[e] > b2) { b2 = p[e]; i2 = e; }

        float ssum = b1 + b2;
        float w1 = b1 / ssum, w2 = b2 / ssum;

        int n0 = token * 2;
        out[n0]     = (float)i1;
        out[n0 + 1] = (float)i2;
        out[NASSIGN + n0]     = w1;
        out[NASSIGN + n0 + 1] = w2;
        out[2 * NASSIGN + 1 + n0]     = 1.0f;
        out[2 * NASSIGN + 1 + n0 + 1] = 1.0f;

        // per-expert bucket append; key = (weight desc, flat idx asc)
        int s1 = atomicAdd(&g_cnt[i1], 1);
        g_bucket[i1][s1] = ((unsigned long long)__float_as_uint(w1) << 32) |
                           (unsigned)(~(unsigned)n0);
        int s2 = atomicAdd(&g_cnt[i2], 1);
        g_bucket[i2][s2] = ((unsigned long long)__float_as_uint(w2) << 32) |
                           (unsigned)(~(unsigned)(n0 + 1));

        #pragma unroll
        for (int e = 0; e < NEXP; e++) atomicAdd(&s_prob[e], p[e]);
    }
    __syncthreads();
    if (tid < NEXP) atomicAdd(&g_probsum[tid], s_prob[tid]);
    __syncthreads();

    // ---- arrival counter: last block finalizes ----
    if (tid == 0) {
        __threadfence();
        unsigned old = atomicAdd(&g_done, 1u);
        s_last = (old == (unsigned)(gridDim.x - 1)) ? 1 : 0;
    }
    __syncthreads();
    if (!s_last) return;

    // All other blocks' writes are visible (threadfence before their arrive).
    __shared__ int cnt[NEXP];
    if (tid < NEXP) cnt[tid] = __ldcg(&g_cnt[tid]);
    __syncthreads();

    if (tid == 0) {
        float imp[NEXP], imps = 0.0f;
        #pragma unroll
        for (int e = 0; e < NEXP; e++) { imp[e] = __ldcg(&g_probsum[e]); imps += imp[e]; }
        float loss = 0.0f;
        #pragma unroll
        for (int e = 0; e < NEXP; e++)
            loss += (imp[e] / imps) * ((float)cnt[e] / (float)NASSIGN);
        out[2 * NASSIGN] = (float)NEXP * loss;
    }

    // Capacity drop (rank = #{j: key > key_i}; keep iff rank < CAP). Matches
    // lexsort((-w, expert)) with flat-index tiebreak; rarely triggers
    // (expected per-expert count ~4096 << 5120).
    for (int e = 0; e < NEXP; e++) {
        int c = cnt[e];
        if (c <= CAP) continue;
        for (int i = tid; i < c; i += blockDim.x) {
            unsigned long long ki = __ldcg(&g_bucket[e][i]);
            int rank = 0;
            for (int j = 0; j < c; j++)
                rank += (__ldcg(&g_bucket[e][j]) > ki) ? 1 : 0;
            if (rank >= CAP) {
                unsigned n = ~(unsigned)(ki & 0xffffffffull);
                out[2 * NASSIGN + 1 + n] = 0.0f;
            }
        }
    }
    __syncthreads();

    // reset scratch for the next graph replay
    if (tid < NEXP) { g_cnt[tid] = 0; g_probsum[tid] = 0.0f; }
    if (tid == 0)   { g_done = 0u; __threadfence(); }
}

extern "C" void kernel_launch(void* const* d_in, const int* in_sizes, int n_in,
                              void* d_out, int out_size) {
    const float* x  = (const float*)d_in[0];
    const float* wg = (const float*)d_in[1];
    float* out = (float*)d_out;
    (void)in_sizes; (void)n_in; (void)out_size;

    cudaFuncSetAttribute(router_main, cudaFuncAttributeMaxDynamicSharedMemorySize,
                         NEXP * DIM * (int)sizeof(float));

    router_main<<<NBLK, 256, NEXP * DIM * sizeof(float)>>>(x, wg, out);
}